// round 8
// baseline (speedup 1.0000x reference)
#include <cuda_runtime.h>
#include <cuda_bf16.h>
#include <math.h>
#include <stdint.h>

// Problem constants
#define BB 4
#define BN 512
#define NROWS 2048

// ---------------- scratch (static device globals; no allocs) ----------------
__device__ float g_Q [NROWS*64];
__device__ float g_K [NROWS*64];   // pre-scaled by DH^-0.5
__device__ float g_V [NROWS*64];
__device__ float g_Q2[NROWS*64];
__device__ float g_K2[NROWS*64];   // pre-scaled
__device__ float g_WE2T[64*64];    // W_E2^T : [hk][d]
__device__ float g_hatt[NROWS*64];

// ---------------- helpers ----------------
__device__ __forceinline__ void mma_bf16(float c[4],
    uint32_t a0, uint32_t a1, uint32_t a2, uint32_t a3,
    uint32_t b0, uint32_t b1)
{
    asm volatile(
        "mma.sync.aligned.m16n8k16.row.col.f32.bf16.bf16.f32 "
        "{%0,%1,%2,%3}, {%4,%5,%6,%7}, {%8,%9}, {%0,%1,%2,%3};"
        : "+f"(c[0]), "+f"(c[1]), "+f"(c[2]), "+f"(c[3])
        : "r"(a0), "r"(a1), "r"(a2), "r"(a3), "r"(b0), "r"(b1));
}

// ---------------- K0: transpose W_E2 ----------------
__global__ void __launch_bounds__(256) k0_init(const float* __restrict__ WE2) {
    int t = threadIdx.x;
    for (int i = t; i < 4096; i += 256) {
        int d = i >> 6, c = i & 63;
        g_WE2T[c*64 + d] = WE2[i];
    }
}

// ---------------- K1: x = LN(h+p); Q,K,V,Q2,K2 projections ----------------
__global__ void __launch_bounds__(64) k1_proj(
    const float* __restrict__ h, const float* __restrict__ p,
    const float* __restrict__ g1, const float* __restrict__ b1,
    const float* __restrict__ WQ, const float* __restrict__ WK,
    const float* __restrict__ WV, const float* __restrict__ WQ2,
    const float* __restrict__ WK2)
{
    int row = blockIdx.x;
    int t = threadIdx.x;
    __shared__ float xs[64];
    __shared__ float red[4];

    float v = h[row*64 + t] + p[row*64 + t];
    float s = v, sq = v*v;
    #pragma unroll
    for (int off = 16; off; off >>= 1) {
        s  += __shfl_down_sync(0xffffffffu, s,  off);
        sq += __shfl_down_sync(0xffffffffu, sq, off);
    }
    int wid = t >> 5, lane = t & 31;
    if (lane == 0) { red[wid*2] = s; red[wid*2+1] = sq; }
    __syncthreads();
    float S  = red[0] + red[2];
    float SQ = red[1] + red[3];
    float mean = S * (1.f/64.f);
    float var  = SQ * (1.f/64.f) - mean*mean;
    float rinv = rsqrtf(var + 1e-5f);
    xs[t] = (v - mean) * rinv * g1[t] + b1[t];
    __syncthreads();

    float q = 0.f, k = 0.f, vv = 0.f, q2 = 0.f, k2 = 0.f;
    #pragma unroll 8
    for (int d = 0; d < 64; ++d) {
        float x = xs[d];
        q  += x * WQ [d*64 + t];
        k  += x * WK [d*64 + t];
        vv += x * WV [d*64 + t];
        q2 += x * WQ2[d*64 + t];
        k2 += x * WK2[d*64 + t];
    }
    const float sc = 0.35355339059327373f;  // 8^-0.5
    g_Q [row*64 + t] = q;
    g_K [row*64 + t] = k * sc;
    g_V [row*64 + t] = vv;
    g_Q2[row*64 + t] = q2;
    g_K2[row*64 + t] = k2 * sc;
}

// ---------------- K2: fully fused scores + softmax-weights + att@V ----------
// Block = one (b,i), 128 threads = 4 warps, 8 j-tiles of 64.
// Dense path: Y = e_tile @ A2^T (bf16 mma), s2 = <Y_row, K2_row>;
// Sparse (adj): s1 via cooperative matvec.
// pw = exp(s)*kRW*mask_j*mask_i accumulated into den[h], pav[h][k] (no global
// max: exp(-mx) cancels between numerator and denominator; scores are O(0.3)).
#define SMSB 72   // bf16 row stride (conflict-free)
#define SMSF 68   // fp32 row stride
#define K2_SMEM (2*64*SMSB*2 + 2*64*SMSF*4)   // 18432 + 34816 = 53248
__global__ void __launch_bounds__(128) k2_fused(
    const float* __restrict__ e, const unsigned* __restrict__ adj,
    const float* __restrict__ WE, const float* __restrict__ kRW,
    const float* __restrict__ mask)
{
    extern __shared__ char dyn[];
    __nv_bfloat16* es  = (__nv_bfloat16*)dyn;                    // [64][SMSB] row=j, col=d
    __nv_bfloat16* A2s = (__nv_bfloat16*)(dyn + 64*SMSB*2);      // [64][SMSB] row=hk, col=d
    float*         K2s = (float*)(dyn + 2*64*SMSB*2);            // [64][SMSF] row=j, col=hk
    float*         Vs  = (float*)(dyn + 2*64*SMSB*2 + 64*SMSF*4);// [64][SMSF] row=j, col=hk

    __shared__ float qs[64], q2s[64];
    __shared__ int lst[64];
    __shared__ int cnt;
    __shared__ unsigned char adjf[64];
    __shared__ float pavsh[64];
    __shared__ float densh[8];

    int bi = blockIdx.x;
    int b = bi >> 9, i = bi & 511;
    int t = threadIdx.x;
    int w = t >> 5, lane = t & 31;
    int r = lane >> 2, cq = lane & 3;
    int m_base = w * 16;

    if (t < 64) qs[t] = g_Q[bi*64 + t];
    else        q2s[t-64] = g_Q2[bi*64 + (t-64)];
    if (t < 64) pavsh[t] = 0.f;
    if (t >= 64 && t < 72) densh[t-64] = 0.f;
    __syncthreads();
    // A2s[hk][d] = W_E2^T[hk][d] * q2[hk], bf16
    #pragma unroll
    for (int it = 0; it < 16; ++it) {
        int idx = t + it*128;              // pair index, 2048 total
        int hk = idx >> 5, dp = idx & 31;
        float2 wv = *(const float2*)&g_WE2T[hk*64 + dp*2];
        float qv = q2s[hk];
        __nv_bfloat162 bv = __floats2bfloat162_rn(wv.x*qv, wv.y*qv);
        *(uint32_t*)&A2s[hk*SMSB + dp*2] = *(uint32_t*)&bv;
    }

    const float4* ebase  = (const float4*)(e + (size_t)bi * BN * 64);
    const float4* k2base = (const float4*)(g_K2 + (size_t)b * BN * 64);
    const float4* vbase  = (const float4*)(g_V  + (size_t)b * BN * 64);
    const float* wp   = kRW  + ((size_t)(b*BN + i))*BN;
    const float* mskp = mask + (size_t)b*BN;
    float mi = mskp[i];

    // per-thread attention accumulators
    float den[8];
    float pav[8][2];
    #pragma unroll
    for (int h = 0; h < 8; ++h) { den[h] = 0.f; pav[h][0] = 0.f; pav[h][1] = 0.f; }

    for (int jt = 0; jt < 8; ++jt) {
        int j0 = jt * 64;
        __syncthreads();       // prior tile fully consumed
        if (t == 0) cnt = 0;
        // stage e tile (fp32 -> bf16), K2 tile, V tile
        #pragma unroll
        for (int it = 0; it < 8; ++it) {
            int idx = t + it*128;          // float4 index, 1024 total
            int jl = idx >> 4, c4 = idx & 15;
            float4 v = ebase[(size_t)(j0 + jl)*16 + c4];
            __nv_bfloat162 lo = __floats2bfloat162_rn(v.x, v.y);
            __nv_bfloat162 hi = __floats2bfloat162_rn(v.z, v.w);
            uint2 pk = { *(uint32_t*)&lo, *(uint32_t*)&hi };
            *(uint2*)&es[jl*SMSB + c4*4] = pk;
            *(float4*)&K2s[jl*SMSF + c4*4] = k2base[(size_t)(j0 + jl)*16 + c4];
            *(float4*)&Vs [jl*SMSF + c4*4] = vbase [(size_t)(j0 + jl)*16 + c4];
        }
        __syncthreads();       // cnt reset + tiles visible
        if (t < 64) {
            unsigned a = adj[(size_t)bi * BN + j0 + t];
            adjf[t] = a ? 1 : 0;
            if (a) { int pos = atomicAdd(&cnt, 1); lst[pos] = t; }
        }
        __syncthreads();       // list/flags ready

        // ---- dense E2 path: warp computes 16 rows x 64 hk, K=64 ----
        float acc[8][4];
        #pragma unroll
        for (int nt = 0; nt < 8; ++nt)
            #pragma unroll
            for (int z = 0; z < 4; ++z) acc[nt][z] = 0.f;

        int a_row0 = (m_base + r)*SMSB;
        int a_row1 = a_row0 + 8*SMSB;
        #pragma unroll
        for (int kc = 0; kc < 4; ++kc) {
            int k0 = kc*16 + cq*2;
            uint32_t a0 = *(const uint32_t*)&es[a_row0 + k0];
            uint32_t a1 = *(const uint32_t*)&es[a_row1 + k0];
            uint32_t a2 = *(const uint32_t*)&es[a_row0 + k0 + 8];
            uint32_t a3 = *(const uint32_t*)&es[a_row1 + k0 + 8];
            #pragma unroll
            for (int nt = 0; nt < 8; ++nt) {
                int n = nt*8 + r;
                uint32_t b0 = *(const uint32_t*)&A2s[n*SMSB + k0];
                uint32_t b1 = *(const uint32_t*)&A2s[n*SMSB + k0 + 8];
                mma_bf16(acc[nt], a0, a1, a2, a3, b0, b1);
            }
        }

        // ---- dense epilogue: s2 -> pw -> den/pav accumulation ----
        int jl0 = m_base + r, jl1 = jl0 + 8;
        float c0 = adjf[jl0] ? 0.f : wp[j0 + jl0] * mskp[j0 + jl0] * mi;
        float c1 = adjf[jl1] ? 0.f : wp[j0 + jl1] * mskp[j0 + jl1] * mi;
        #pragma unroll
        for (int h = 0; h < 8; ++h) {
            float2 ka = *(const float2*)&K2s[jl0*SMSF + h*8 + 2*cq];
            float2 kb = *(const float2*)&K2s[jl1*SMSF + h*8 + 2*cq];
            float s0 = acc[h][0]*ka.x + acc[h][1]*ka.y;
            float s1 = acc[h][2]*kb.x + acc[h][3]*kb.y;
            s0 += __shfl_xor_sync(0xffffffffu, s0, 1);
            s0 += __shfl_xor_sync(0xffffffffu, s0, 2);
            s1 += __shfl_xor_sync(0xffffffffu, s1, 1);
            s1 += __shfl_xor_sync(0xffffffffu, s1, 2);
            float pw0 = __expf(s0) * c0;
            float pw1 = __expf(s1) * c1;
            den[h] += pw0 + pw1;
            float2 v0 = *(const float2*)&Vs[jl0*SMSF + h*8 + 2*cq];
            float2 v1 = *(const float2*)&Vs[jl1*SMSF + h*8 + 2*cq];
            pav[h][0] += pw0*v0.x + pw1*v1.x;
            pav[h][1] += pw0*v0.y + pw1*v1.y;
        }

        // ---- sparse E path: one adj column per warp ----
        int n = cnt;
        for (int q = w; q < n; q += 4) {
            int jl = lst[q];
            int j = j0 + jl;
            float y0 = 0.f, y1 = 0.f;
            #pragma unroll 8
            for (int d = 0; d < 64; ++d) {
                float ev = __bfloat162float(es[jl*SMSB + d]);
                y0 += ev * WE[d*64 + lane];
                y1 += ev * WE[d*64 + 32 + lane];
            }
            y0 *= qs[lane];
            y1 *= qs[lane + 32];
            const float* kp = &g_K[((size_t)(b*BN + j))*64];
            float z0 = y0 * kp[lane];
            float z1 = y1 * kp[lane + 32];
            z0 += __shfl_xor_sync(0xffffffffu, z0, 1);
            z0 += __shfl_xor_sync(0xffffffffu, z0, 2);
            z0 += __shfl_xor_sync(0xffffffffu, z0, 4);
            z1 += __shfl_xor_sync(0xffffffffu, z1, 1);
            z1 += __shfl_xor_sync(0xffffffffu, z1, 2);
            z1 += __shfl_xor_sync(0xffffffffu, z1, 4);
            float wfac = wp[j] * mskp[j] * mi;
            float pw0 = __expf(z0) * wfac;   // heads 0-3 (hk = lane)
            float pw1 = __expf(z1) * wfac;   // heads 4-7 (hk = lane+32)
            atomicAdd(&pavsh[lane],      pw0 * Vs[jl*SMSF + lane]);
            atomicAdd(&pavsh[lane + 32], pw1 * Vs[jl*SMSF + lane + 32]);
            if ((lane & 7) == 0) {
                atomicAdd(&densh[lane >> 3],       pw0);
                atomicAdd(&densh[4 + (lane >> 3)], pw1);
            }
        }
    }

    // ---- fold dense accumulators: reduce over r (lane bits 2..4) ----
    #pragma unroll
    for (int h = 0; h < 8; ++h) {
        #pragma unroll
        for (int o = 4; o <= 16; o <<= 1) {
            den[h]    += __shfl_xor_sync(0xffffffffu, den[h],    o);
            pav[h][0] += __shfl_xor_sync(0xffffffffu, pav[h][0], o);
            pav[h][1] += __shfl_xor_sync(0xffffffffu, pav[h][1], o);
        }
    }
    if (r == 0) {   // lanes 0-3 hold totals for their cq
        #pragma unroll
        for (int h = 0; h < 8; ++h) {
            atomicAdd(&pavsh[h*8 + 2*cq],     pav[h][0]);
            atomicAdd(&pavsh[h*8 + 2*cq + 1], pav[h][1]);
            if (cq == 0) atomicAdd(&densh[h], den[h]);
        }
    }
    __syncthreads();
    if (t < 64)
        g_hatt[(size_t)bi*64 + t] = pavsh[t] / fmaxf(densh[t >> 3], 1e-6f);
}

// ---------------- K5: O-proj + residual + LN2 + FFN + residual ----------------
__global__ void __launch_bounds__(64) k5_out(
    const float* __restrict__ hin, const float* __restrict__ OW,
    const float* __restrict__ Ob, const float* __restrict__ g2,
    const float* __restrict__ b2, const float* __restrict__ Wf1,
    const float* __restrict__ bf1, const float* __restrict__ Wf2,
    const float* __restrict__ bf2, float* __restrict__ out)
{
    int row = blockIdx.x;
    int t = threadIdx.x;
    __shared__ float has[64], ys[64], hid[128];
    __shared__ float red[4];

    has[t] = g_hatt[row*64 + t];
    __syncthreads();

    float a = hin[row*64 + t] + Ob[t];
    #pragma unroll 8
    for (int d = 0; d < 64; ++d) a += has[d] * OW[d*64 + t];

    float s = a, sq = a*a;
    #pragma unroll
    for (int off = 16; off; off >>= 1) {
        s  += __shfl_down_sync(0xffffffffu, s,  off);
        sq += __shfl_down_sync(0xffffffffu, sq, off);
    }
    int wid = t >> 5, lane = t & 31;
    if (lane == 0) { red[wid*2] = s; red[wid*2+1] = sq; }
    __syncthreads();
    float S  = red[0] + red[2];
    float SQ = red[1] + red[3];
    float mean = S * (1.f/64.f);
    float var  = SQ * (1.f/64.f) - mean*mean;
    float rinv = rsqrtf(var + 1e-5f);
    ys[t] = (a - mean) * rinv * g2[t] + b2[t];
    __syncthreads();

    float h0 = bf1[t], h1 = bf1[t + 64];
    #pragma unroll 8
    for (int d = 0; d < 64; ++d) {
        float x = ys[d];
        h0 += x * Wf1[d*128 + t];
        h1 += x * Wf1[d*128 + t + 64];
    }
    hid[t]      = fmaxf(h0, 0.f);
    hid[t + 64] = fmaxf(h1, 0.f);
    __syncthreads();

    float o = a + bf2[t];
    #pragma unroll 8
    for (int c = 0; c < 128; ++c) o += hid[c] * Wf2[c*64 + t];
    out[row*64 + t] = o;
}

// ---------------- launch ----------------
extern "C" void kernel_launch(void* const* d_in, const int* in_sizes, int n_in,
                              void* d_out, int out_size)
{
    const float* h    = (const float*)d_in[0];
    const float* p    = (const float*)d_in[1];
    const float* e    = (const float*)d_in[2];
    const float* kRW  = (const float*)d_in[3];
    const float* mask = (const float*)d_in[4];
    const unsigned* adj = (const unsigned*)d_in[5];
    const float* WQ   = (const float*)d_in[6];
    const float* WK   = (const float*)d_in[7];
    const float* WV   = (const float*)d_in[8];
    const float* WQ2  = (const float*)d_in[9];
    const float* WK2  = (const float*)d_in[10];
    const float* WE   = (const float*)d_in[11];
    const float* WE2  = (const float*)d_in[12];
    const float* OW   = (const float*)d_in[13];
    const float* Ob   = (const float*)d_in[14];
    const float* g1   = (const float*)d_in[15];
    const float* b1   = (const float*)d_in[16];
    const float* g2   = (const float*)d_in[17];
    const float* b2   = (const float*)d_in[18];
    const float* Wf1  = (const float*)d_in[19];
    const float* bf1  = (const float*)d_in[20];
    const float* Wf2  = (const float*)d_in[21];
    const float* bf2  = (const float*)d_in[22];
    float* out = (float*)d_out;

    cudaFuncSetAttribute(k2_fused, cudaFuncAttributeMaxDynamicSharedMemorySize, K2_SMEM);

    k0_init<<<1, 256>>>(WE2);
    k1_proj<<<NROWS, 64>>>(h, p, g1, b1, WQ, WK, WV, WQ2, WK2);
    k2_fused<<<NROWS, 128, K2_SMEM>>>(e, adj, WE, kRW, mask);
    k5_out<<<NROWS, 64>>>(h, OW, Ob, g2, b2, Wf1, bf1, Wf2, bf2, out);
}

// round 9
// speedup vs baseline: 1.1843x; 1.1843x over previous
#include <cuda_runtime.h>
#include <cuda_bf16.h>
#include <math.h>
#include <stdint.h>

// Problem constants
#define BB 4
#define BN 512
#define BH 32
#define NROWS 2048

// ---------------- scratch (static device globals; no allocs) ----------------
__device__ float g_Q [NROWS*64];
__device__ float g_K [NROWS*64];   // pre-scaled by DH^-0.5
__device__ float g_VT[BB*64*BN];   // V transposed: [b][c][j]
__device__ float g_Q2[NROWS*64];
__device__ float g_K2[NROWS*64];   // pre-scaled
__device__ float g_WE2T[64*64];    // W_E2^T : [hk][d]
__device__ float g_scores[(size_t)BH*BN*BN];  // 33.5 MB
__device__ float g_hatt[NROWS*64];

// ---------------- helpers ----------------
__device__ __forceinline__ void mma_bf16(float c[4],
    uint32_t a0, uint32_t a1, uint32_t a2, uint32_t a3,
    uint32_t b0, uint32_t b1)
{
    asm volatile(
        "mma.sync.aligned.m16n8k16.row.col.f32.bf16.bf16.f32 "
        "{%0,%1,%2,%3}, {%4,%5,%6,%7}, {%8,%9}, {%0,%1,%2,%3};"
        : "+f"(c[0]), "+f"(c[1]), "+f"(c[2]), "+f"(c[3])
        : "r"(a0), "r"(a1), "r"(a2), "r"(a3), "r"(b0), "r"(b1));
}

// ---------------- K0: transpose W_E2 ----------------
__global__ void __launch_bounds__(256) k0_init(const float* __restrict__ WE2) {
    int t = threadIdx.x;
    for (int i = t; i < 4096; i += 256) {
        int d = i >> 6, c = i & 63;
        g_WE2T[c*64 + d] = WE2[i];
    }
}

// ---------------- K1: x = LN(h+p); Q,K,V,Q2,K2 projections ----------------
__global__ void __launch_bounds__(64) k1_proj(
    const float* __restrict__ h, const float* __restrict__ p,
    const float* __restrict__ g1, const float* __restrict__ b1,
    const float* __restrict__ WQ, const float* __restrict__ WK,
    const float* __restrict__ WV, const float* __restrict__ WQ2,
    const float* __restrict__ WK2)
{
    int row = blockIdx.x;
    int b = row >> 9, n = row & 511;
    int t = threadIdx.x;
    __shared__ float xs[64];
    __shared__ float red[4];

    float v = h[row*64 + t] + p[row*64 + t];
    float s = v, sq = v*v;
    #pragma unroll
    for (int off = 16; off; off >>= 1) {
        s  += __shfl_down_sync(0xffffffffu, s,  off);
        sq += __shfl_down_sync(0xffffffffu, sq, off);
    }
    int wid = t >> 5, lane = t & 31;
    if (lane == 0) { red[wid*2] = s; red[wid*2+1] = sq; }
    __syncthreads();
    float S  = red[0] + red[2];
    float SQ = red[1] + red[3];
    float mean = S * (1.f/64.f);
    float var  = SQ * (1.f/64.f) - mean*mean;
    float rinv = rsqrtf(var + 1e-5f);
    xs[t] = (v - mean) * rinv * g1[t] + b1[t];
    __syncthreads();

    float q = 0.f, k = 0.f, vv = 0.f, q2 = 0.f, k2 = 0.f;
    #pragma unroll 8
    for (int d = 0; d < 64; ++d) {
        float x = xs[d];
        q  += x * WQ [d*64 + t];
        k  += x * WK [d*64 + t];
        vv += x * WV [d*64 + t];
        q2 += x * WQ2[d*64 + t];
        k2 += x * WK2[d*64 + t];
    }
    const float sc = 0.35355339059327373f;  // 8^-0.5
    g_Q [row*64 + t] = q;
    g_K [row*64 + t] = k * sc;
    g_VT[((size_t)b*64 + t)*512 + n] = vv;
    g_Q2[row*64 + t] = q2;
    g_K2[row*64 + t] = k2 * sc;
}

// ---------------- K2: bf16 m16n8k16 tensor-core fused scores ----------------
// (round-5/7 proven version: 35KB smem, high occupancy)
#define SMSB 72   // bf16 row stride for es/A2s (conflict-free)
#define SMSF 68   // fp32 row stride for K2s
__global__ void __launch_bounds__(128) k2_scores(
    const float* __restrict__ e, const unsigned* __restrict__ adj,
    const float* __restrict__ WE)
{
    extern __shared__ char dyn[];
    __nv_bfloat16* es  = (__nv_bfloat16*)dyn;                    // [64][SMSB] row=j, col=d
    __nv_bfloat16* A2s = (__nv_bfloat16*)(dyn + 64*SMSB*2);      // [64][SMSB] row=hk, col=d
    float*         K2s = (float*)        (dyn + 2*64*SMSB*2);    // [64][SMSF] row=j, col=hk

    __shared__ float qs[64], q2s[64];
    __shared__ int lst[64];
    __shared__ int cnt;
    __shared__ unsigned char adjf[64];

    int bi = blockIdx.x;
    int b = bi >> 9, i = bi & 511;
    int t = threadIdx.x;
    int w = t >> 5, lane = t & 31;
    int r = lane >> 2, cq = lane & 3;
    int m_base = w * 16;

    if (t < 64) qs[t] = g_Q[bi*64 + t];
    else        q2s[t-64] = g_Q2[bi*64 + (t-64)];
    __syncthreads();
    // A2s[hk][d] = W_E2^T[hk][d] * q2[hk], bf16
    #pragma unroll
    for (int it = 0; it < 16; ++it) {
        int idx = t + it*128;              // pair index, 2048 total
        int hk = idx >> 5, dp = idx & 31;
        float2 wv = *(const float2*)&g_WE2T[hk*64 + dp*2];
        float qv = q2s[hk];
        __nv_bfloat162 bv = __floats2bfloat162_rn(wv.x*qv, wv.y*qv);
        *(uint32_t*)&A2s[hk*SMSB + dp*2] = *(uint32_t*)&bv;
    }

    const float4* ebase  = (const float4*)(e + (size_t)bi * BN * 64);
    const float4* k2base = (const float4*)(g_K2 + (size_t)b * BN * 64);

    for (int jt = 0; jt < 8; ++jt) {
        int j0 = jt * 64;
        __syncthreads();       // prior tile fully consumed (also covers A2s build)
        if (t == 0) cnt = 0;
        // stage e tile (fp32 -> bf16) and K2 tile (fp32)
        #pragma unroll
        for (int it = 0; it < 8; ++it) {
            int idx = t + it*128;          // float4 index, 1024 total
            int jl = idx >> 4, c4 = idx & 15;
            float4 v = ebase[(size_t)(j0 + jl)*16 + c4];
            __nv_bfloat162 lo = __floats2bfloat162_rn(v.x, v.y);
            __nv_bfloat162 hi = __floats2bfloat162_rn(v.z, v.w);
            uint2 pk = { *(uint32_t*)&lo, *(uint32_t*)&hi };
            *(uint2*)&es[jl*SMSB + c4*4] = pk;
            float4 kv = k2base[(size_t)(j0 + jl)*16 + c4];
            *(float4*)&K2s[jl*SMSF + c4*4] = kv;
        }
        __syncthreads();       // cnt reset + tiles visible
        if (t < 64) {
            unsigned a = adj[(size_t)bi * BN + j0 + t];
            adjf[t] = a ? 1 : 0;
            if (a) { int pos = atomicAdd(&cnt, 1); lst[pos] = t; }
        }
        __syncthreads();       // list/flags ready

        // ---- dense E2 path: warp computes 16 rows x 64 hk, K=64 ----
        float acc[8][4];
        #pragma unroll
        for (int nt = 0; nt < 8; ++nt)
            #pragma unroll
            for (int z = 0; z < 4; ++z) acc[nt][z] = 0.f;

        int a_row0 = (m_base + r)*SMSB;
        int a_row1 = a_row0 + 8*SMSB;
        #pragma unroll
        for (int kc = 0; kc < 4; ++kc) {
            int k0 = kc*16 + cq*2;
            uint32_t a0 = *(const uint32_t*)&es[a_row0 + k0];
            uint32_t a1 = *(const uint32_t*)&es[a_row1 + k0];
            uint32_t a2 = *(const uint32_t*)&es[a_row0 + k0 + 8];
            uint32_t a3 = *(const uint32_t*)&es[a_row1 + k0 + 8];
            #pragma unroll
            for (int nt = 0; nt < 8; ++nt) {
                int n = nt*8 + r;
                uint32_t b0 = *(const uint32_t*)&A2s[n*SMSB + k0];
                uint32_t b1 = *(const uint32_t*)&A2s[n*SMSB + k0 + 8];
                mma_bf16(acc[nt], a0, a1, a2, a3, b0, b1);
            }
        }

        // ---- epilogue: score[h,j] = sum_k Y[j,h*8+k]*K2[j,h*8+k] ----
        int jl0 = m_base + r, jl1 = jl0 + 8;
        #pragma unroll
        for (int h = 0; h < 8; ++h) {
            float2 ka = *(const float2*)&K2s[jl0*SMSF + h*8 + 2*cq];
            float2 kb = *(const float2*)&K2s[jl1*SMSF + h*8 + 2*cq];
            float s0 = acc[h][0]*ka.x + acc[h][1]*ka.y;
            float s1 = acc[h][2]*kb.x + acc[h][3]*kb.y;
            s0 += __shfl_xor_sync(0xffffffffu, s0, 1);
            s0 += __shfl_xor_sync(0xffffffffu, s0, 2);
            s1 += __shfl_xor_sync(0xffffffffu, s1, 1);
            s1 += __shfl_xor_sync(0xffffffffu, s1, 2);
            if (cq == 0) {
                size_t srow = ((size_t)(b*8 + h)*BN + i)*BN + j0;
                if (!adjf[jl0]) g_scores[srow + jl0] = s0;
                if (!adjf[jl1]) g_scores[srow + jl1] = s1;
            }
        }

        // ---- sparse E path: one adj column per warp ----
        int n = cnt;
        for (int q = w; q < n; q += 4) {
            int jl = lst[q];
            int j = j0 + jl;
            float y0 = 0.f, y1 = 0.f;
            #pragma unroll 8
            for (int d = 0; d < 64; ++d) {
                float ev = __bfloat162float(es[jl*SMSB + d]);
                y0 += ev * WE[d*64 + lane];
                y1 += ev * WE[d*64 + 32 + lane];
            }
            y0 *= qs[lane];
            y1 *= qs[lane + 32];
            const float* kp = &g_K[((size_t)(b*BN + j))*64];
            float z0 = y0 * kp[lane];
            float z1 = y1 * kp[lane + 32];
            z0 += __shfl_xor_sync(0xffffffffu, z0, 1);
            z0 += __shfl_xor_sync(0xffffffffu, z0, 2);
            z0 += __shfl_xor_sync(0xffffffffu, z0, 4);
            z1 += __shfl_xor_sync(0xffffffffu, z1, 1);
            z1 += __shfl_xor_sync(0xffffffffu, z1, 2);
            z1 += __shfl_xor_sync(0xffffffffu, z1, 4);
            if ((lane & 7) == 0) {
                int h0 = lane >> 3;  // heads 0..3 (z0), 4..7 (z1)
                g_scores[((size_t)(b*8 + h0    )*BN + i)*BN + j] = z0;
                g_scores[((size_t)(b*8 + h0 + 4)*BN + i)*BN + j] = z1;
            }
        }
    }
}
#define K2_SMEM (2*64*SMSB*2 + 64*SMSF*4)   // 18432 + 17408 = 35840

// ---------------- K4: exp/mask/k_RW + rowsum + att@V -------------------------
// No global max (exp(-mx) cancels num/denom; validated rounds 7 vs 8).
// Block = (b,h, 8 i-rows). 8 warps, one i each. V-head tile (8x512, 16KB)
// staged in smem and shared by all warps: inner loop = 2 LDG + 9 LDS.
__global__ void __launch_bounds__(256) k4_att(
    const float* __restrict__ kRW, const float* __restrict__ mask)
{
    __shared__ float Vs[8*512];   // 16 KB
    __shared__ float msk[512];
    int bh = blockIdx.y;                  // 0..31
    int b = bh >> 3, h = bh & 7;
    int i0 = blockIdx.x * 8;              // grid.x = 64
    int t = threadIdx.x, w = t >> 5, lane = t & 31;

    const float4* vtp = (const float4*)(g_VT + ((size_t)(b*64) + h*8)*512);
    #pragma unroll
    for (int idx = t; idx < 1024; idx += 256)
        ((float4*)Vs)[idx] = vtp[idx];
    for (int j = t; j < 512; j += 256) msk[j] = mask[b*512 + j];
    __syncthreads();

    int i = i0 + w;
    float mi = msk[i];
    const float* sp = g_scores + ((size_t)(b*8 + h)*512 + i)*512;
    const float* wp = kRW + ((size_t)(b*512 + i))*512;

    float pden = 0.f;
    float pav[8];
    #pragma unroll
    for (int k = 0; k < 8; ++k) pav[k] = 0.f;

    #pragma unroll 4
    for (int jt = 0; jt < 16; ++jt) {
        int j = jt*32 + lane;
        float pw = __expf(sp[j]) * wp[j] * msk[j] * mi;
        pden += pw;
        #pragma unroll
        for (int k = 0; k < 8; ++k) pav[k] += pw * Vs[k*512 + j];
    }
    #pragma unroll
    for (int off = 16; off; off >>= 1) {
        pden += __shfl_down_sync(0xffffffffu, pden, off);
        #pragma unroll
        for (int k = 0; k < 8; ++k) pav[k] += __shfl_down_sync(0xffffffffu, pav[k], off);
    }
    if (lane == 0) {
        float inv = 1.f / fmaxf(pden, 1e-6f);
        float4* op = (float4*)&g_hatt[((size_t)(b*512 + i))*64 + h*8];
        op[0] = make_float4(pav[0]*inv, pav[1]*inv, pav[2]*inv, pav[3]*inv);
        op[1] = make_float4(pav[4]*inv, pav[5]*inv, pav[6]*inv, pav[7]*inv);
    }
}

// ---------------- K5: O-proj + residual + LN2 + FFN + residual ----------------
__global__ void __launch_bounds__(64) k5_out(
    const float* __restrict__ hin, const float* __restrict__ OW,
    const float* __restrict__ Ob, const float* __restrict__ g2,
    const float* __restrict__ b2, const float* __restrict__ Wf1,
    const float* __restrict__ bf1, const float* __restrict__ Wf2,
    const float* __restrict__ bf2, float* __restrict__ out)
{
    int row = blockIdx.x;
    int t = threadIdx.x;
    __shared__ float has[64], ys[64], hid[128];
    __shared__ float red[4];

    has[t] = g_hatt[row*64 + t];
    __syncthreads();

    float a = hin[row*64 + t] + Ob[t];
    #pragma unroll 8
    for (int d = 0; d < 64; ++d) a += has[d] * OW[d*64 + t];

    float s = a, sq = a*a;
    #pragma unroll
    for (int off = 16; off; off >>= 1) {
        s  += __shfl_down_sync(0xffffffffu, s,  off);
        sq += __shfl_down_sync(0xffffffffu, sq, off);
    }
    int wid = t >> 5, lane = t & 31;
    if (lane == 0) { red[wid*2] = s; red[wid*2+1] = sq; }
    __syncthreads();
    float S  = red[0] + red[2];
    float SQ = red[1] + red[3];
    float mean = S * (1.f/64.f);
    float var  = SQ * (1.f/64.f) - mean*mean;
    float rinv = rsqrtf(var + 1e-5f);
    ys[t] = (a - mean) * rinv * g2[t] + b2[t];
    __syncthreads();

    float h0 = bf1[t], h1 = bf1[t + 64];
    #pragma unroll 8
    for (int d = 0; d < 64; ++d) {
        float x = ys[d];
        h0 += x * Wf1[d*128 + t];
        h1 += x * Wf1[d*128 + t + 64];
    }
    hid[t]      = fmaxf(h0, 0.f);
    hid[t + 64] = fmaxf(h1, 0.f);
    __syncthreads();

    float o = a + bf2[t];
    #pragma unroll 8
    for (int c = 0; c < 128; ++c) o += hid[c] * Wf2[c*64 + t];
    out[row*64 + t] = o;
}

// ---------------- launch ----------------
extern "C" void kernel_launch(void* const* d_in, const int* in_sizes, int n_in,
                              void* d_out, int out_size)
{
    const float* h    = (const float*)d_in[0];
    const float* p    = (const float*)d_in[1];
    const float* e    = (const float*)d_in[2];
    const float* kRW  = (const float*)d_in[3];
    const float* mask = (const float*)d_in[4];
    const unsigned* adj = (const unsigned*)d_in[5];
    const float* WQ   = (const float*)d_in[6];
    const float* WK   = (const float*)d_in[7];
    const float* WV   = (const float*)d_in[8];
    const float* WQ2  = (const float*)d_in[9];
    const float* WK2  = (const float*)d_in[10];
    const float* WE   = (const float*)d_in[11];
    const float* WE2  = (const float*)d_in[12];
    const float* OW   = (const float*)d_in[13];
    const float* Ob   = (const float*)d_in[14];
    const float* g1   = (const float*)d_in[15];
    const float* b1   = (const float*)d_in[16];
    const float* g2   = (const float*)d_in[17];
    const float* b2   = (const float*)d_in[18];
    const float* Wf1  = (const float*)d_in[19];
    const float* bf1  = (const float*)d_in[20];
    const float* Wf2  = (const float*)d_in[21];
    const float* bf2  = (const float*)d_in[22];
    float* out = (float*)d_out;

    cudaFuncSetAttribute(k2_scores, cudaFuncAttributeMaxDynamicSharedMemorySize, K2_SMEM);

    k0_init<<<1, 256>>>(WE2);
    k1_proj<<<NROWS, 64>>>(h, p, g1, b1, WQ, WK, WV, WQ2, WK2);
    k2_scores<<<NROWS, 128, K2_SMEM>>>(e, adj, WE);
    k4_att<<<dim3(64, 32), 256>>>(kRW, mask);
    k5_out<<<NROWS, 64>>>(h, OW, Ob, g2, b2, Wf1, bf1, Wf2, bf2, out);
}

// round 10
// speedup vs baseline: 1.6637x; 1.4048x over previous
#include <cuda_runtime.h>
#include <cuda_bf16.h>
#include <cuda_fp16.h>
#include <math.h>
#include <stdint.h>

// Problem constants
#define BB 4
#define BN 512
#define BH 32
#define NROWS 2048

// ---------------- scratch (static device globals; no allocs) ----------------
__device__ float g_Q [NROWS*64];
__device__ float g_K [NROWS*64];   // pre-scaled by DH^-0.5
__device__ float g_VT[BB*64*BN];   // V transposed: [b][c][j]
__device__ float g_Q2[NROWS*64];
__device__ float g_K2[NROWS*64];   // pre-scaled
__device__ float g_WET [64*64];    // W_E^T  : [hk][d]
__device__ float g_WE2T[64*64];    // W_E2^T : [hk][d]
__device__ __half g_scores[(size_t)BH*BN*BN];  // 67 MB
__device__ float g_hatt[NROWS*64];

// ---------------- helpers ----------------
__device__ __forceinline__ void mma_bf16(float c[4],
    uint32_t a0, uint32_t a1, uint32_t a2, uint32_t a3,
    uint32_t b0, uint32_t b1)
{
    asm volatile(
        "mma.sync.aligned.m16n8k16.row.col.f32.bf16.bf16.f32 "
        "{%0,%1,%2,%3}, {%4,%5,%6,%7}, {%8,%9}, {%0,%1,%2,%3};"
        : "+f"(c[0]), "+f"(c[1]), "+f"(c[2]), "+f"(c[3])
        : "r"(a0), "r"(a1), "r"(a2), "r"(a3), "r"(b0), "r"(b1));
}

#define SMSB 72   // bf16 smem row stride (conflict-free)

// ---------------- K0: transpose W_E, W_E2 ----------------
__global__ void __launch_bounds__(256) k0_init(const float* __restrict__ WE,
                                               const float* __restrict__ WE2) {
    int t = threadIdx.x;
    for (int i = t; i < 4096; i += 256) {
        int d = i >> 6, c = i & 63;
        g_WET [c*64 + d] = WE [i];
        g_WE2T[c*64 + d] = WE2[i];
    }
}

// ---------------- K1: x = LN(h+p); Q,K,V,Q2,K2 projections ----------------
__global__ void __launch_bounds__(64) k1_proj(
    const float* __restrict__ h, const float* __restrict__ p,
    const float* __restrict__ g1, const float* __restrict__ b1,
    const float* __restrict__ WQ, const float* __restrict__ WK,
    const float* __restrict__ WV, const float* __restrict__ WQ2,
    const float* __restrict__ WK2)
{
    int row = blockIdx.x;
    int b = row >> 9, n = row & 511;
    int t = threadIdx.x;
    __shared__ float xs[64];
    __shared__ float red[4];

    float v = h[row*64 + t] + p[row*64 + t];
    float s = v, sq = v*v;
    #pragma unroll
    for (int off = 16; off; off >>= 1) {
        s  += __shfl_down_sync(0xffffffffu, s,  off);
        sq += __shfl_down_sync(0xffffffffu, sq, off);
    }
    int wid = t >> 5, lane = t & 31;
    if (lane == 0) { red[wid*2] = s; red[wid*2+1] = sq; }
    __syncthreads();
    float S  = red[0] + red[2];
    float SQ = red[1] + red[3];
    float mean = S * (1.f/64.f);
    float var  = SQ * (1.f/64.f) - mean*mean;
    float rinv = rsqrtf(var + 1e-5f);
    xs[t] = (v - mean) * rinv * g1[t] + b1[t];
    __syncthreads();

    float q = 0.f, k = 0.f, vv = 0.f, q2 = 0.f, k2 = 0.f;
    #pragma unroll 8
    for (int d = 0; d < 64; ++d) {
        float x = xs[d];
        q  += x * WQ [d*64 + t];
        k  += x * WK [d*64 + t];
        vv += x * WV [d*64 + t];
        q2 += x * WQ2[d*64 + t];
        k2 += x * WK2[d*64 + t];
    }
    const float sc = 0.35355339059327373f;  // 8^-0.5
    g_Q [row*64 + t] = q;
    g_K [row*64 + t] = k * sc;
    g_VT[((size_t)b*64 + t)*512 + n] = vv;
    g_Q2[row*64 + t] = q2;
    g_K2[row*64 + t] = k2 * sc;
}

// ---------------- K2a: dense E2 scores (GEMM only, unconditional stores) -----
// Block = one (b,i), 128 threads = 4 warps, 8 j-tiles of 64.
// smem: es bf16[64][72] + A2s bf16[64][72] = 18432 B (high occupancy).
// K2 epilogue fragments read directly from L2 (prefetched pre-mma).
#define K2_SMEM (2*64*SMSB*2)
__global__ void __launch_bounds__(128) k2_dense(const float* __restrict__ e)
{
    extern __shared__ char dyn[];
    __nv_bfloat16* es  = (__nv_bfloat16*)dyn;               // [64][SMSB] row=j, col=d
    __nv_bfloat16* A2s = (__nv_bfloat16*)(dyn + 64*SMSB*2); // [64][SMSB] row=hk, col=d
    __shared__ float q2s[64];

    int bi = blockIdx.x;
    int b = bi >> 9, i = bi & 511;
    int t = threadIdx.x;
    int w = t >> 5, lane = t & 31;
    int r = lane >> 2, cq = lane & 3;
    int m0 = w * 16;

    if (t < 64) q2s[t] = g_Q2[bi*64 + t];
    __syncthreads();
    // A2s[hk][d] = W_E2^T[hk][d] * q2[hk], bf16
    #pragma unroll
    for (int it = 0; it < 16; ++it) {
        int idx = t + it*128;
        int hk = idx >> 5, dp = idx & 31;
        float2 wv = *(const float2*)&g_WE2T[hk*64 + dp*2];
        float qv = q2s[hk];
        __nv_bfloat162 bv = __floats2bfloat162_rn(wv.x*qv, wv.y*qv);
        *(uint32_t*)&A2s[hk*SMSB + dp*2] = *(uint32_t*)&bv;
    }

    const float4* ebase = (const float4*)(e + (size_t)bi * BN * 64);
    int jl0 = m0 + r, jl1 = jl0 + 8;

    for (int jt = 0; jt < 8; ++jt) {
        int j0 = jt * 64;
        __syncthreads();      // es free (covers A2s build on first iter)
        #pragma unroll
        for (int it = 0; it < 8; ++it) {
            int idx = t + it*128;
            int jl = idx >> 4, c4 = idx & 15;
            float4 v = ebase[(size_t)(j0 + jl)*16 + c4];
            __nv_bfloat162 lo = __floats2bfloat162_rn(v.x, v.y);
            __nv_bfloat162 hi = __floats2bfloat162_rn(v.z, v.w);
            uint2 pk = { *(uint32_t*)&lo, *(uint32_t*)&hi };
            *(uint2*)&es[jl*SMSB + c4*4] = pk;
        }
        __syncthreads();

        // prefetch K2 fragments for this tile (L2-hot, hidden behind mma)
        const float* kr0 = g_K2 + ((size_t)(b*512 + j0 + jl0))*64 + 2*cq;
        const float* kr1 = g_K2 + ((size_t)(b*512 + j0 + jl1))*64 + 2*cq;
        float2 ka[8], kb[8];
        #pragma unroll
        for (int h = 0; h < 8; ++h) {
            ka[h] = __ldg((const float2*)(kr0 + h*8));
            kb[h] = __ldg((const float2*)(kr1 + h*8));
        }

        float acc[8][4];
        #pragma unroll
        for (int nt = 0; nt < 8; ++nt)
            #pragma unroll
            for (int z = 0; z < 4; ++z) acc[nt][z] = 0.f;

        int a_row0 = jl0*SMSB;
        int a_row1 = jl1*SMSB;
        #pragma unroll
        for (int kc = 0; kc < 4; ++kc) {
            int k0 = kc*16 + cq*2;
            uint32_t a0 = *(const uint32_t*)&es[a_row0 + k0];
            uint32_t a1 = *(const uint32_t*)&es[a_row1 + k0];
            uint32_t a2 = *(const uint32_t*)&es[a_row0 + k0 + 8];
            uint32_t a3 = *(const uint32_t*)&es[a_row1 + k0 + 8];
            #pragma unroll
            for (int nt = 0; nt < 8; ++nt) {
                int n = nt*8 + r;
                uint32_t b0 = *(const uint32_t*)&A2s[n*SMSB + k0];
                uint32_t b1 = *(const uint32_t*)&A2s[n*SMSB + k0 + 8];
                mma_bf16(acc[nt], a0, a1, a2, a3, b0, b1);
            }
        }

        // epilogue: score[h,j] = <Y[j,h*8..], K2[j,h*8..]>, unconditional store
        #pragma unroll
        for (int h = 0; h < 8; ++h) {
            float s0 = acc[h][0]*ka[h].x + acc[h][1]*ka[h].y;
            float s1 = acc[h][2]*kb[h].x + acc[h][3]*kb[h].y;
            s0 += __shfl_xor_sync(0xffffffffu, s0, 1);
            s0 += __shfl_xor_sync(0xffffffffu, s0, 2);
            s1 += __shfl_xor_sync(0xffffffffu, s1, 1);
            s1 += __shfl_xor_sync(0xffffffffu, s1, 2);
            if (cq == 0) {
                size_t srow = ((size_t)(b*8 + h)*BN + i)*BN + j0;
                g_scores[srow + jl0] = __float2half(s0);
                g_scores[srow + jl1] = __float2half(s1);
            }
        }
    }
}

// ---------------- K2b: sparse E path via gather + mma, overwrites adj cells --
// Block = one (b,i). Gather adj columns (avg 25.6; P(>64)~1e-11) into one
// 64-row tile; Y1 = tile @ (W_E^T o Q); s1 = <Y1, K>. Fallback loop for >64.
__global__ void __launch_bounds__(128) k2_sparse(
    const float* __restrict__ e, const unsigned* __restrict__ adj)
{
    extern __shared__ char dyn[];
    __nv_bfloat16* es  = (__nv_bfloat16*)dyn;
    __nv_bfloat16* A1s = (__nv_bfloat16*)(dyn + 64*SMSB*2);
    __shared__ float qs[64];
    __shared__ int lst[128];
    __shared__ int cnt;

    int bi = blockIdx.x;
    int b = bi >> 9, i = bi & 511;
    int t = threadIdx.x;
    int w = t >> 5, lane = t & 31;
    int r = lane >> 2, cq = lane & 3;
    int m0 = w * 16;

    if (t < 64) qs[t] = g_Q[bi*64 + t];
    if (t == 0) cnt = 0;
    __syncthreads();

    // scan adj row, build list
    #pragma unroll
    for (int it = 0; it < 4; ++it) {
        int j = t + it*128;
        if (adj[(size_t)bi*512 + j]) {
            int pos = atomicAdd(&cnt, 1);
            if (pos < 128) lst[pos] = j;
        }
    }
    // A1s[hk][d] = W_E^T[hk][d] * q[hk]
    #pragma unroll
    for (int it = 0; it < 16; ++it) {
        int idx = t + it*128;
        int hk = idx >> 5, dp = idx & 31;
        float2 wv = *(const float2*)&g_WET[hk*64 + dp*2];
        float qv = qs[hk];
        __nv_bfloat162 bv = __floats2bfloat162_rn(wv.x*qv, wv.y*qv);
        *(uint32_t*)&A1s[hk*SMSB + dp*2] = *(uint32_t*)&bv;
    }
    __syncthreads();
    int n = cnt;
    int ng = n < 64 ? n : 64;

    // gather adj e-rows (zero-pad beyond ng)
    #pragma unroll
    for (int it = 0; it < 8; ++it) {
        int idx = t + it*128;
        int q = idx >> 4, c4 = idx & 15;
        float4 v = make_float4(0.f, 0.f, 0.f, 0.f);
        if (q < ng) {
            int j = lst[q];
            v = *(const float4*)(e + ((size_t)bi*512 + j)*64 + c4*4);
        }
        __nv_bfloat162 lo = __floats2bfloat162_rn(v.x, v.y);
        __nv_bfloat162 hi = __floats2bfloat162_rn(v.z, v.w);
        uint2 pk = { *(uint32_t*)&lo, *(uint32_t*)&hi };
        *(uint2*)&es[q*SMSB + c4*4] = pk;
    }
    __syncthreads();

    int q0 = m0 + r, q1 = q0 + 8;
    bool v0 = q0 < ng, v1 = q1 < ng;
    int j0v = v0 ? lst[q0] : 0;
    int j1v = v1 ? lst[q1] : 0;
    const float* kr0 = g_K + ((size_t)(b*512 + j0v))*64 + 2*cq;
    const float* kr1 = g_K + ((size_t)(b*512 + j1v))*64 + 2*cq;
    float2 ka[8], kb[8];
    #pragma unroll
    for (int h = 0; h < 8; ++h) {
        ka[h] = __ldg((const float2*)(kr0 + h*8));
        kb[h] = __ldg((const float2*)(kr1 + h*8));
    }

    float acc[8][4];
    #pragma unroll
    for (int nt = 0; nt < 8; ++nt)
        #pragma unroll
        for (int z = 0; z < 4; ++z) acc[nt][z] = 0.f;

    int a_row0 = q0*SMSB, a_row1 = q1*SMSB;
    #pragma unroll
    for (int kc = 0; kc < 4; ++kc) {
        int k0 = kc*16 + cq*2;
        uint32_t a0 = *(const uint32_t*)&es[a_row0 + k0];
        uint32_t a1 = *(const uint32_t*)&es[a_row1 + k0];
        uint32_t a2 = *(const uint32_t*)&es[a_row0 + k0 + 8];
        uint32_t a3 = *(const uint32_t*)&es[a_row1 + k0 + 8];
        #pragma unroll
        for (int nt = 0; nt < 8; ++nt) {
            int nn = nt*8 + r;
            uint32_t b0 = *(const uint32_t*)&A1s[nn*SMSB + k0];
            uint32_t b1 = *(const uint32_t*)&A1s[nn*SMSB + k0 + 8];
            mma_bf16(acc[nt], a0, a1, a2, a3, b0, b1);
        }
    }

    #pragma unroll
    for (int h = 0; h < 8; ++h) {
        float s0 = acc[h][0]*ka[h].x + acc[h][1]*ka[h].y;
        float s1 = acc[h][2]*kb[h].x + acc[h][3]*kb[h].y;
        s0 += __shfl_xor_sync(0xffffffffu, s0, 1);
        s0 += __shfl_xor_sync(0xffffffffu, s0, 2);
        s1 += __shfl_xor_sync(0xffffffffu, s1, 1);
        s1 += __shfl_xor_sync(0xffffffffu, s1, 2);
        if (cq == 0) {
            size_t srow = ((size_t)(b*8 + h)*BN + i)*BN;
            if (v0) g_scores[srow + j0v] = __float2half(s0);
            if (v1) g_scores[srow + j1v] = __float2half(s1);
        }
    }

    // fallback for pathological rows (>64 adj): cooperative, rarely executes
    if (n > 64) {
        int nf = n < 128 ? n : 128;
        for (int q = 64 + w; q < nf; q += 4) {
            int j = lst[q];
            const float* ep = e + ((size_t)bi*512 + j)*64;
            float y0 = 0.f, y1 = 0.f;
            for (int d = 0; d < 64; ++d) {
                float ev = ep[d];
                y0 += ev * g_WET[lane*64 + d];
                y1 += ev * g_WET[(lane+32)*64 + d];
            }
            y0 *= qs[lane];
            y1 *= qs[lane + 32];
            const float* kp = g_K + ((size_t)(b*512 + j))*64;
            float z0 = y0 * kp[lane];
            float z1 = y1 * kp[lane + 32];
            z0 += __shfl_xor_sync(0xffffffffu, z0, 1);
            z0 += __shfl_xor_sync(0xffffffffu, z0, 2);
            z0 += __shfl_xor_sync(0xffffffffu, z0, 4);
            z1 += __shfl_xor_sync(0xffffffffu, z1, 1);
            z1 += __shfl_xor_sync(0xffffffffu, z1, 2);
            z1 += __shfl_xor_sync(0xffffffffu, z1, 4);
            if ((lane & 7) == 0) {
                int h0 = lane >> 3;
                g_scores[((size_t)(b*8 + h0    )*BN + i)*BN + j] = __float2half(z0);
                g_scores[((size_t)(b*8 + h0 + 4)*BN + i)*BN + j] = __float2half(z1);
            }
        }
    }
}

// ---------------- K4: exp/mask/k_RW + rowsum + att@V (half scores) -----------
__global__ void __launch_bounds__(256) k4_att(
    const float* __restrict__ kRW, const float* __restrict__ mask)
{
    __shared__ float Vs[8*512];   // 16 KB
    __shared__ float msk[512];
    int bh = blockIdx.y;
    int b = bh >> 3, h = bh & 7;
    int i0 = blockIdx.x * 8;
    int t = threadIdx.x, w = t >> 5, lane = t & 31;

    const float4* vtp = (const float4*)(g_VT + ((size_t)(b*64) + h*8)*512);
    #pragma unroll
    for (int idx = t; idx < 1024; idx += 256)
        ((float4*)Vs)[idx] = vtp[idx];
    for (int j = t; j < 512; j += 256) msk[j] = mask[b*512 + j];
    __syncthreads();

    int i = i0 + w;
    float mi = msk[i];
    const __half* sp = g_scores + ((size_t)(b*8 + h)*512 + i)*512;
    const float* wp = kRW + ((size_t)(b*512 + i))*512;

    float pden = 0.f;
    float pav[8];
    #pragma unroll
    for (int k = 0; k < 8; ++k) pav[k] = 0.f;

    #pragma unroll 4
    for (int jt = 0; jt < 16; ++jt) {
        int j = jt*32 + lane;
        float pw = __expf(__half2float(sp[j])) * wp[j] * msk[j] * mi;
        pden += pw;
        #pragma unroll
        for (int k = 0; k < 8; ++k) pav[k] += pw * Vs[k*512 + j];
    }
    #pragma unroll
    for (int off = 16; off; off >>= 1) {
        pden += __shfl_down_sync(0xffffffffu, pden, off);
        #pragma unroll
        for (int k = 0; k < 8; ++k) pav[k] += __shfl_down_sync(0xffffffffu, pav[k], off);
    }
    if (lane == 0) {
        float inv = 1.f / fmaxf(pden, 1e-6f);
        float4* op = (float4*)&g_hatt[((size_t)(b*512 + i))*64 + h*8];
        op[0] = make_float4(pav[0]*inv, pav[1]*inv, pav[2]*inv, pav[3]*inv);
        op[1] = make_float4(pav[4]*inv, pav[5]*inv, pav[6]*inv, pav[7]*inv);
    }
}

// ---------------- K5: O-proj + residual + LN2 + FFN + residual ----------------
__global__ void __launch_bounds__(64) k5_out(
    const float* __restrict__ hin, const float* __restrict__ OW,
    const float* __restrict__ Ob, const float* __restrict__ g2,
    const float* __restrict__ b2, const float* __restrict__ Wf1,
    const float* __restrict__ bf1, const float* __restrict__ Wf2,
    const float* __restrict__ bf2, float* __restrict__ out)
{
    int row = blockIdx.x;
    int t = threadIdx.x;
    __shared__ float has[64], ys[64], hid[128];
    __shared__ float red[4];

    has[t] = g_hatt[row*64 + t];
    __syncthreads();

    float a = hin[row*64 + t] + Ob[t];
    #pragma unroll 8
    for (int d = 0; d < 64; ++d) a += has[d] * OW[d*64 + t];

    float s = a, sq = a*a;
    #pragma unroll
    for (int off = 16; off; off >>= 1) {
        s  += __shfl_down_sync(0xffffffffu, s,  off);
        sq += __shfl_down_sync(0xffffffffu, sq, off);
    }
    int wid = t >> 5, lane = t & 31;
    if (lane == 0) { red[wid*2] = s; red[wid*2+1] = sq; }
    __syncthreads();
    float S  = red[0] + red[2];
    float SQ = red[1] + red[3];
    float mean = S * (1.f/64.f);
    float var  = SQ * (1.f/64.f) - mean*mean;
    float rinv = rsqrtf(var + 1e-5f);
    ys[t] = (a - mean) * rinv * g2[t] + b2[t];
    __syncthreads();

    float h0 = bf1[t], h1 = bf1[t + 64];
    #pragma unroll 8
    for (int d = 0; d < 64; ++d) {
        float x = ys[d];
        h0 += x * Wf1[d*128 + t];
        h1 += x * Wf1[d*128 + t + 64];
    }
    hid[t]      = fmaxf(h0, 0.f);
    hid[t + 64] = fmaxf(h1, 0.f);
    __syncthreads();

    float o = a + bf2[t];
    #pragma unroll 8
    for (int c = 0; c < 128; ++c) o += hid[c] * Wf2[c*64 + t];
    out[row*64 + t] = o;
}

// ---------------- launch ----------------
extern "C" void kernel_launch(void* const* d_in, const int* in_sizes, int n_in,
                              void* d_out, int out_size)
{
    const float* h    = (const float*)d_in[0];
    const float* p    = (const float*)d_in[1];
    const float* e    = (const float*)d_in[2];
    const float* kRW  = (const float*)d_in[3];
    const float* mask = (const float*)d_in[4];
    const unsigned* adj = (const unsigned*)d_in[5];
    const float* WQ   = (const float*)d_in[6];
    const float* WK   = (const float*)d_in[7];
    const float* WV   = (const float*)d_in[8];
    const float* WQ2  = (const float*)d_in[9];
    const float* WK2  = (const float*)d_in[10];
    const float* WE   = (const float*)d_in[11];
    const float* WE2  = (const float*)d_in[12];
    const float* OW   = (const float*)d_in[13];
    const float* Ob   = (const float*)d_in[14];
    const float* g1   = (const float*)d_in[15];
    const float* b1   = (const float*)d_in[16];
    const float* g2   = (const float*)d_in[17];
    const float* b2   = (const float*)d_in[18];
    const float* Wf1  = (const float*)d_in[19];
    const float* bf1  = (const float*)d_in[20];
    const float* Wf2  = (const float*)d_in[21];
    const float* bf2  = (const float*)d_in[22];
    float* out = (float*)d_out;

    k0_init<<<1, 256>>>(WE, WE2);
    k1_proj<<<NROWS, 64>>>(h, p, g1, b1, WQ, WK, WV, WQ2, WK2);
    k2_dense<<<NROWS, 128, K2_SMEM>>>(e);
    k2_sparse<<<NROWS, 128, K2_SMEM>>>(e, adj);
    k4_att<<<dim3(64, 32), 256>>>(kRW, mask);
    k5_out<<<NROWS, 64>>>(h, OW, Ob, g2, b2, Wf1, bf1, Wf2, bf2, out);
}

// round 11
// speedup vs baseline: 1.6954x; 1.0191x over previous
#include <cuda_runtime.h>
#include <cuda_bf16.h>
#include <cuda_fp16.h>
#include <math.h>
#include <stdint.h>

// Problem constants
#define BB 4
#define BN 512
#define BH 32
#define NROWS 2048

// ---------------- scratch (static device globals; no allocs) ----------------
__device__ float g_Q [NROWS*64];
__device__ float g_K [NROWS*64];   // pre-scaled by DH^-0.5
__device__ float g_VT[BB*64*BN];   // V transposed: [b][c][j]
__device__ float g_Q2[NROWS*64];
__device__ float g_K2[NROWS*64];   // pre-scaled
__device__ float g_WET [64*64];    // W_E^T  : [hk][d]
__device__ float g_WE2T[64*64];    // W_E2^T : [hk][d]
__device__ __half g_scores[(size_t)BH*BN*BN];
__device__ float g_hatt[NROWS*64];

// ---------------- helpers ----------------
__device__ __forceinline__ void mma_bf16(float c[4],
    uint32_t a0, uint32_t a1, uint32_t a2, uint32_t a3,
    uint32_t b0, uint32_t b1)
{
    asm volatile(
        "mma.sync.aligned.m16n8k16.row.col.f32.bf16.bf16.f32 "
        "{%0,%1,%2,%3}, {%4,%5,%6,%7}, {%8,%9}, {%0,%1,%2,%3};"
        : "+f"(c[0]), "+f"(c[1]), "+f"(c[2]), "+f"(c[3])
        : "r"(a0), "r"(a1), "r"(a2), "r"(a3), "r"(b0), "r"(b1));
}

#define SMSB 72   // bf16 smem row stride (conflict-free)

// ---------------- K0: transpose W_E, W_E2 ----------------
__global__ void __launch_bounds__(256) k0_init(const float* __restrict__ WE,
                                               const float* __restrict__ WE2) {
    int t = threadIdx.x;
    for (int i = t; i < 4096; i += 256) {
        int d = i >> 6, c = i & 63;
        g_WET [c*64 + d] = WE [i];
        g_WE2T[c*64 + d] = WE2[i];
    }
}

// ---------------- K1: x = LN(h+p); projections. 4 rows/block ----------------
__global__ void __launch_bounds__(256) k1_proj(
    const float* __restrict__ h, const float* __restrict__ p,
    const float* __restrict__ g1, const float* __restrict__ b1,
    const float* __restrict__ WQ, const float* __restrict__ WK,
    const float* __restrict__ WV, const float* __restrict__ WQ2,
    const float* __restrict__ WK2)
{
    int ty = threadIdx.y;
    int row = blockIdx.x*4 + ty;
    int b = row >> 9, n = row & 511;
    int t = threadIdx.x;
    __shared__ float xs[4][64];
    __shared__ float red[4][4];

    float v = h[row*64 + t] + p[row*64 + t];
    float s = v, sq = v*v;
    #pragma unroll
    for (int off = 16; off; off >>= 1) {
        s  += __shfl_down_sync(0xffffffffu, s,  off);
        sq += __shfl_down_sync(0xffffffffu, sq, off);
    }
    int wid = t >> 5, lane = t & 31;
    if (lane == 0) { red[ty][wid*2] = s; red[ty][wid*2+1] = sq; }
    __syncthreads();
    float S  = red[ty][0] + red[ty][2];
    float SQ = red[ty][1] + red[ty][3];
    float mean = S * (1.f/64.f);
    float var  = SQ * (1.f/64.f) - mean*mean;
    float rinv = rsqrtf(var + 1e-5f);
    xs[ty][t] = (v - mean) * rinv * g1[t] + b1[t];
    __syncthreads();

    float q = 0.f, k = 0.f, vv = 0.f, q2 = 0.f, k2 = 0.f;
    #pragma unroll 8
    for (int d = 0; d < 64; ++d) {
        float x = xs[ty][d];
        q  += x * WQ [d*64 + t];
        k  += x * WK [d*64 + t];
        vv += x * WV [d*64 + t];
        q2 += x * WQ2[d*64 + t];
        k2 += x * WK2[d*64 + t];
    }
    const float sc = 0.35355339059327373f;  // 8^-0.5
    g_Q [row*64 + t] = q;
    g_K [row*64 + t] = k * sc;
    g_VT[((size_t)b*64 + t)*512 + n] = vv;
    g_Q2[row*64 + t] = q2;
    g_K2[row*64 + t] = k2 * sc;
}

// ---------------- K2a: dense E2 scores, register double-buffered ------------
// Block = one (b,i), 128 threads = 4 warps, 8 j-tiles of 64.
// Tile t+1 prefetched into regs during tile t's mma; ONE barrier per tile.
// smem: es[2] bf16[64][72] + A2s bf16[64][72] = 27648 B.
#define K2_SMEM (3*64*SMSB*2)
__global__ void __launch_bounds__(128) k2_dense(const float* __restrict__ e)
{
    extern __shared__ char dyn[];
    __nv_bfloat16* esb[2];
    esb[0] = (__nv_bfloat16*)dyn;
    esb[1] = (__nv_bfloat16*)(dyn + 64*SMSB*2);
    __nv_bfloat16* A2s = (__nv_bfloat16*)(dyn + 2*64*SMSB*2);
    __shared__ float q2s[64];

    int bi = blockIdx.x;
    int b = bi >> 9, i = bi & 511;
    int t = threadIdx.x;
    int lane = t & 31;
    int r = lane >> 2, cq = lane & 3;
    int m0 = (t >> 5) * 16;

    const float4* ebase = (const float4*)(e + (size_t)bi * BN * 64);

    // prologue: start tile-0 loads immediately
    float4 rv[8];
    #pragma unroll
    for (int it = 0; it < 8; ++it) rv[it] = ebase[t + it*128];

    if (t < 64) q2s[t] = g_Q2[bi*64 + t];
    __syncthreads();
    // A2s[hk][d] = W_E2^T[hk][d] * q2[hk], bf16
    #pragma unroll
    for (int it = 0; it < 16; ++it) {
        int idx = t + it*128;
        int hk = idx >> 5, dp = idx & 31;
        float2 wv = *(const float2*)&g_WE2T[hk*64 + dp*2];
        float qv = q2s[hk];
        __nv_bfloat162 bv = __floats2bfloat162_rn(wv.x*qv, wv.y*qv);
        *(uint32_t*)&A2s[hk*SMSB + dp*2] = *(uint32_t*)&bv;
    }
    // store tile 0
    #pragma unroll
    for (int it = 0; it < 8; ++it) {
        int idx = t + it*128;
        int jl = idx >> 4, c4 = idx & 15;
        float4 v = rv[it];
        __nv_bfloat162 lo = __floats2bfloat162_rn(v.x, v.y);
        __nv_bfloat162 hi = __floats2bfloat162_rn(v.z, v.w);
        uint2 pk = { *(uint32_t*)&lo, *(uint32_t*)&hi };
        *(uint2*)&esb[0][jl*SMSB + c4*4] = pk;
    }
    __syncthreads();

    int jl0 = m0 + r, jl1 = jl0 + 8;

    for (int tt = 0; tt < 8; ++tt) {
        int j0 = tt * 64;
        // prefetch next tile into regs (latency hides under mma)
        if (tt < 7) {
            #pragma unroll
            for (int it = 0; it < 8; ++it)
                rv[it] = ebase[(size_t)(j0 + 64)*16 + t + it*128];
        }

        const __nv_bfloat16* es = esb[tt & 1];
        float acc[8][4];
        #pragma unroll
        for (int nt = 0; nt < 8; ++nt)
            #pragma unroll
            for (int z = 0; z < 4; ++z) acc[nt][z] = 0.f;

        int a_row0 = jl0*SMSB;
        int a_row1 = jl1*SMSB;
        #pragma unroll
        for (int kc = 0; kc < 4; ++kc) {
            int k0 = kc*16 + cq*2;
            uint32_t a0 = *(const uint32_t*)&es[a_row0 + k0];
            uint32_t a1 = *(const uint32_t*)&es[a_row1 + k0];
            uint32_t a2 = *(const uint32_t*)&es[a_row0 + k0 + 8];
            uint32_t a3 = *(const uint32_t*)&es[a_row1 + k0 + 8];
            #pragma unroll
            for (int nt = 0; nt < 8; ++nt) {
                int n = nt*8 + r;
                uint32_t b0 = *(const uint32_t*)&A2s[n*SMSB + k0];
                uint32_t b1 = *(const uint32_t*)&A2s[n*SMSB + k0 + 8];
                mma_bf16(acc[nt], a0, a1, a2, a3, b0, b1);
            }
        }

        // epilogue: K2 fragments per-h from L2 (hot)
        const float* kr0 = g_K2 + ((size_t)(b*512 + j0 + jl0))*64 + 2*cq;
        const float* kr1 = g_K2 + ((size_t)(b*512 + j0 + jl1))*64 + 2*cq;
        #pragma unroll
        for (int h = 0; h < 8; ++h) {
            float2 ka = __ldg((const float2*)(kr0 + h*8));
            float2 kb = __ldg((const float2*)(kr1 + h*8));
            float s0 = acc[h][0]*ka.x + acc[h][1]*ka.y;
            float s1 = acc[h][2]*kb.x + acc[h][3]*kb.y;
            s0 += __shfl_xor_sync(0xffffffffu, s0, 1);
            s0 += __shfl_xor_sync(0xffffffffu, s0, 2);
            s1 += __shfl_xor_sync(0xffffffffu, s1, 1);
            s1 += __shfl_xor_sync(0xffffffffu, s1, 2);
            if (cq == 0) {
                size_t srow = ((size_t)(b*8 + h)*BN + i)*BN + j0;
                g_scores[srow + jl0] = __float2half(s0);
                g_scores[srow + jl1] = __float2half(s1);
            }
        }

        // stage next tile into the other buffer; one barrier per tile
        if (tt < 7) {
            __nv_bfloat16* nb = esb[(tt + 1) & 1];
            #pragma unroll
            for (int it = 0; it < 8; ++it) {
                int idx = t + it*128;
                int jl = idx >> 4, c4 = idx & 15;
                float4 v = rv[it];
                __nv_bfloat162 lo = __floats2bfloat162_rn(v.x, v.y);
                __nv_bfloat162 hi = __floats2bfloat162_rn(v.z, v.w);
                uint2 pk = { *(uint32_t*)&lo, *(uint32_t*)&hi };
                *(uint2*)&nb[jl*SMSB + c4*4] = pk;
            }
            __syncthreads();
        }
    }
}

// ---------------- K2b: sparse E path via gather + mma (round-10 proven) -----
#define K2S_SMEM (2*64*SMSB*2)
__global__ void __launch_bounds__(128) k2_sparse(
    const float* __restrict__ e, const unsigned* __restrict__ adj)
{
    extern __shared__ char dyn[];
    __nv_bfloat16* es  = (__nv_bfloat16*)dyn;
    __nv_bfloat16* A1s = (__nv_bfloat16*)(dyn + 64*SMSB*2);
    __shared__ float qs[64];
    __shared__ int lst[128];
    __shared__ int cnt;

    int bi = blockIdx.x;
    int b = bi >> 9, i = bi & 511;
    int t = threadIdx.x;
    int w = t >> 5, lane = t & 31;
    int r = lane >> 2, cq = lane & 3;
    int m0 = w * 16;

    if (t < 64) qs[t] = g_Q[bi*64 + t];
    if (t == 0) cnt = 0;
    __syncthreads();

    #pragma unroll
    for (int it = 0; it < 4; ++it) {
        int j = t + it*128;
        if (adj[(size_t)bi*512 + j]) {
            int pos = atomicAdd(&cnt, 1);
            if (pos < 128) lst[pos] = j;
        }
    }
    #pragma unroll
    for (int it = 0; it < 16; ++it) {
        int idx = t + it*128;
        int hk = idx >> 5, dp = idx & 31;
        float2 wv = *(const float2*)&g_WET[hk*64 + dp*2];
        float qv = qs[hk];
        __nv_bfloat162 bv = __floats2bfloat162_rn(wv.x*qv, wv.y*qv);
        *(uint32_t*)&A1s[hk*SMSB + dp*2] = *(uint32_t*)&bv;
    }
    __syncthreads();
    int n = cnt;
    int ng = n < 64 ? n : 64;

    #pragma unroll
    for (int it = 0; it < 8; ++it) {
        int idx = t + it*128;
        int q = idx >> 4, c4 = idx & 15;
        float4 v = make_float4(0.f, 0.f, 0.f, 0.f);
        if (q < ng) {
            int j = lst[q];
            v = *(const float4*)(e + ((size_t)bi*512 + j)*64 + c4*4);
        }
        __nv_bfloat162 lo = __floats2bfloat162_rn(v.x, v.y);
        __nv_bfloat162 hi = __floats2bfloat162_rn(v.z, v.w);
        uint2 pk = { *(uint32_t*)&lo, *(uint32_t*)&hi };
        *(uint2*)&es[q*SMSB + c4*4] = pk;
    }
    __syncthreads();

    int q0 = m0 + r, q1 = q0 + 8;
    bool v0 = q0 < ng, v1 = q1 < ng;
    int j0v = v0 ? lst[q0] : 0;
    int j1v = v1 ? lst[q1] : 0;
    const float* kr0 = g_K + ((size_t)(b*512 + j0v))*64 + 2*cq;
    const float* kr1 = g_K + ((size_t)(b*512 + j1v))*64 + 2*cq;
    float2 ka[8], kb[8];
    #pragma unroll
    for (int h = 0; h < 8; ++h) {
        ka[h] = __ldg((const float2*)(kr0 + h*8));
        kb[h] = __ldg((const float2*)(kr1 + h*8));
    }

    float acc[8][4];
    #pragma unroll
    for (int nt = 0; nt < 8; ++nt)
        #pragma unroll
        for (int z = 0; z < 4; ++z) acc[nt][z] = 0.f;

    int a_row0 = q0*SMSB, a_row1 = q1*SMSB;
    #pragma unroll
    for (int kc = 0; kc < 4; ++kc) {
        int k0 = kc*16 + cq*2;
        uint32_t a0 = *(const uint32_t*)&es[a_row0 + k0];
        uint32_t a1 = *(const uint32_t*)&es[a_row1 + k0];
        uint32_t a2 = *(const uint32_t*)&es[a_row0 + k0 + 8];
        uint32_t a3 = *(const uint32_t*)&es[a_row1 + k0 + 8];
        #pragma unroll
        for (int nt = 0; nt < 8; ++nt) {
            int nn = nt*8 + r;
            uint32_t b0 = *(const uint32_t*)&A1s[nn*SMSB + k0];
            uint32_t b1 = *(const uint32_t*)&A1s[nn*SMSB + k0 + 8];
            mma_bf16(acc[nt], a0, a1, a2, a3, b0, b1);
        }
    }

    #pragma unroll
    for (int h = 0; h < 8; ++h) {
        float s0 = acc[h][0]*ka[h].x + acc[h][1]*ka[h].y;
        float s1 = acc[h][2]*kb[h].x + acc[h][3]*kb[h].y;
        s0 += __shfl_xor_sync(0xffffffffu, s0, 1);
        s0 += __shfl_xor_sync(0xffffffffu, s0, 2);
        s1 += __shfl_xor_sync(0xffffffffu, s1, 1);
        s1 += __shfl_xor_sync(0xffffffffu, s1, 2);
        if (cq == 0) {
            size_t srow = ((size_t)(b*8 + h)*BN + i)*BN;
            if (v0) g_scores[srow + j0v] = __float2half(s0);
            if (v1) g_scores[srow + j1v] = __float2half(s1);
        }
    }

    if (n > 64) {   // pathological fallback, statistically never
        int nf = n < 128 ? n : 128;
        for (int q = 64 + w; q < nf; q += 4) {
            int j = lst[q];
            const float* ep = e + ((size_t)bi*512 + j)*64;
            float y0 = 0.f, y1 = 0.f;
            for (int d = 0; d < 64; ++d) {
                float ev = ep[d];
                y0 += ev * g_WET[lane*64 + d];
                y1 += ev * g_WET[(lane+32)*64 + d];
            }
            y0 *= qs[lane];
            y1 *= qs[lane + 32];
            const float* kp = g_K + ((size_t)(b*512 + j))*64;
            float z0 = y0 * kp[lane];
            float z1 = y1 * kp[lane + 32];
            z0 += __shfl_xor_sync(0xffffffffu, z0, 1);
            z0 += __shfl_xor_sync(0xffffffffu, z0, 2);
            z0 += __shfl_xor_sync(0xffffffffu, z0, 4);
            z1 += __shfl_xor_sync(0xffffffffu, z1, 1);
            z1 += __shfl_xor_sync(0xffffffffu, z1, 2);
            z1 += __shfl_xor_sync(0xffffffffu, z1, 4);
            if ((lane & 7) == 0) {
                int h0 = lane >> 3;
                g_scores[((size_t)(b*8 + h0    )*BN + i)*BN + j] = __float2half(z0);
                g_scores[((size_t)(b*8 + h0 + 4)*BN + i)*BN + j] = __float2half(z1);
            }
        }
    }
}

// ---------------- K4: exp/mask/k_RW + rowsum + att@V (half scores) -----------
__global__ void __launch_bounds__(256) k4_att(
    const float* __restrict__ kRW, const float* __restrict__ mask)
{
    __shared__ float Vs[8*512];   // 16 KB
    __shared__ float msk[512];
    int bh = blockIdx.y;
    int b = bh >> 3, h = bh & 7;
    int i0 = blockIdx.x * 8;
    int t = threadIdx.x, w = t >> 5, lane = t & 31;

    const float4* vtp = (const float4*)(g_VT + ((size_t)(b*64) + h*8)*512);
    #pragma unroll
    for (int idx = t; idx < 1024; idx += 256)
        ((float4*)Vs)[idx] = vtp[idx];
    for (int j = t; j < 512; j += 256) msk[j] = mask[b*512 + j];
    __syncthreads();

    int i = i0 + w;
    float mi = msk[i];
    const __half* sp = g_scores + ((size_t)(b*8 + h)*512 + i)*512;
    const float* wp = kRW + ((size_t)(b*512 + i))*512;

    float pden = 0.f;
    float pav[8];
    #pragma unroll
    for (int k = 0; k < 8; ++k) pav[k] = 0.f;

    #pragma unroll 4
    for (int jt = 0; jt < 16; ++jt) {
        int j = jt*32 + lane;
        float pw = __expf(__half2float(sp[j])) * wp[j] * msk[j] * mi;
        pden += pw;
        #pragma unroll
        for (int k = 0; k < 8; ++k) pav[k] += pw * Vs[k*512 + j];
    }
    #pragma unroll
    for (int off = 16; off; off >>= 1) {
        pden += __shfl_down_sync(0xffffffffu, pden, off);
        #pragma unroll
        for (int k = 0; k < 8; ++k) pav[k] += __shfl_down_sync(0xffffffffu, pav[k], off);
    }
    if (lane == 0) {
        float inv = 1.f / fmaxf(pden, 1e-6f);
        float4* op = (float4*)&g_hatt[((size_t)(b*512 + i))*64 + h*8];
        op[0] = make_float4(pav[0]*inv, pav[1]*inv, pav[2]*inv, pav[3]*inv);
        op[1] = make_float4(pav[4]*inv, pav[5]*inv, pav[6]*inv, pav[7]*inv);
    }
}

// ---------------- K5: O-proj + LN2 + FFN + residuals. 4 rows/block ----------
__global__ void __launch_bounds__(256) k5_out(
    const float* __restrict__ hin, const float* __restrict__ OW,
    const float* __restrict__ Ob, const float* __restrict__ g2,
    const float* __restrict__ b2, const float* __restrict__ Wf1,
    const float* __restrict__ bf1, const float* __restrict__ Wf2,
    const float* __restrict__ bf2, float* __restrict__ out)
{
    int ty = threadIdx.y;
    int row = blockIdx.x*4 + ty;
    int t = threadIdx.x;
    __shared__ float has[4][64], ys[4][64], hid[4][128];
    __shared__ float red[4][4];

    has[ty][t] = g_hatt[row*64 + t];
    __syncthreads();

    float a = hin[row*64 + t] + Ob[t];
    #pragma unroll 8
    for (int d = 0; d < 64; ++d) a += has[ty][d] * OW[d*64 + t];

    float s = a, sq = a*a;
    #pragma unroll
    for (int off = 16; off; off >>= 1) {
        s  += __shfl_down_sync(0xffffffffu, s,  off);
        sq += __shfl_down_sync(0xffffffffu, sq, off);
    }
    int wid = t >> 5, lane = t & 31;
    if (lane == 0) { red[ty][wid*2] = s; red[ty][wid*2+1] = sq; }
    __syncthreads();
    float S  = red[ty][0] + red[ty][2];
    float SQ = red[ty][1] + red[ty][3];
    float mean = S * (1.f/64.f);
    float var  = SQ * (1.f/64.f) - mean*mean;
    float rinv = rsqrtf(var + 1e-5f);
    ys[ty][t] = (a - mean) * rinv * g2[t] + b2[t];
    __syncthreads();

    float h0 = bf1[t], h1 = bf1[t + 64];
    #pragma unroll 8
    for (int d = 0; d < 64; ++d) {
        float x = ys[ty][d];
        h0 += x * Wf1[d*128 + t];
        h1 += x * Wf1[d*128 + t + 64];
    }
    hid[ty][t]      = fmaxf(h0, 0.f);
    hid[ty][t + 64] = fmaxf(h1, 0.f);
    __syncthreads();

    float o = a + bf2[t];
    #pragma unroll 8
    for (int c = 0; c < 128; ++c) o += hid[ty][c] * Wf2[c*64 + t];
    out[row*64 + t] = o;
}

// ---------------- launch ----------------
extern "C" void kernel_launch(void* const* d_in, const int* in_sizes, int n_in,
                              void* d_out, int out_size)
{
    const float* h    = (const float*)d_in[0];
    const float* p    = (const float*)d_in[1];
    const float* e    = (const float*)d_in[2];
    const float* kRW  = (const float*)d_in[3];
    const float* mask = (const float*)d_in[4];
    const unsigned* adj = (const unsigned*)d_in[5];
    const float* WQ   = (const float*)d_in[6];
    const float* WK   = (const float*)d_in[7];
    const float* WV   = (const float*)d_in[8];
    const float* WQ2  = (const float*)d_in[9];
    const float* WK2  = (const float*)d_in[10];
    const float* WE   = (const float*)d_in[11];
    const float* WE2  = (const float*)d_in[12];
    const float* OW   = (const float*)d_in[13];
    const float* Ob   = (const float*)d_in[14];
    const float* g1   = (const float*)d_in[15];
    const float* b1   = (const float*)d_in[16];
    const float* g2   = (const float*)d_in[17];
    const float* b2   = (const float*)d_in[18];
    const float* Wf1  = (const float*)d_in[19];
    const float* bf1  = (const float*)d_in[20];
    const float* Wf2  = (const float*)d_in[21];
    const float* bf2  = (const float*)d_in[22];
    float* out = (float*)d_out;

    k0_init<<<1, 256>>>(WE, WE2);
    k1_proj<<<512, dim3(64,4)>>>(h, p, g1, b1, WQ, WK, WV, WQ2, WK2);
    k2_dense<<<NROWS, 128, K2_SMEM>>>(e);
    k2_sparse<<<NROWS, 128, K2S_SMEM>>>(e, adj);
    k4_att<<<dim3(64, 32), 256>>>(kRW, mask);
    k5_out<<<512, dim3(64,4)>>>(h, OW, Ob, g2, b2, Wf1, bf1, Wf2, bf2, out);
}